// round 15
// baseline (speedup 1.0000x reference)
// Net_76244259439077 — FINAL (R14-equivalent, machine-bound)
// 25-step spiking ConvLSTM×3 + Leaky FC×2, fp32.
// Single persistent DAG kernel; fma pipe measured at ~102% of the scalar
// FFMA issue ceiling (ncu packed-normalized 51.0%) => at the fp32 work bound.
#include <cuda_runtime.h>

#define THR  0.05f
#define BETA 0.9181805491303656f
#define TSTEPS 25
#define BATCH  64

// ---------------- persistent state (module device memory; no allocations) ----
#define N1 (BATCH*16*16*128)   // 2,097,152
#define N2 (BATCH*32*8*64)     // 1,048,576
#define N3 (BATCH*64*4*32)     //   524,288

__device__ float g_syn1[N1];
__device__ float g_mem1[2][N1];
__device__ float g_spk1[2][BATCH*16*8*64];
__device__ float g_syn2[N2];
__device__ float g_mem2[2][N2];
__device__ float g_spk2[2][BATCH*32*4*32];
__device__ float g_syn3[N3];
__device__ float g_mem3[2][N3];
__device__ float g_spk3[2][BATCH*64*2*16];
__device__ float g_mem4[BATCH*512];
__device__ float g_spk4[2][BATCH*512];
__device__ float g_mem5[BATCH*2];

// Aggregate counters: [stage][t] (3=FC1, 4=FC2)
__device__ int g_cnt[5][TSTEPS];
// Per-batch counters: [conv stage 0..2][t][b]
__device__ int g_cb[3][TSTEPS][BATCH];
// L3 per-half counters: [t][half] (half = batch>>5), for FC1 deps
__device__ int g_l3h[TSTEPS][2];

// Repacked weights: [gch][ic][12] (taps 0..8, pad 9..11 = 0), 16B-aligned rows
__device__ __align__(16) float g_wp_1[64  * 17 * 12];
__device__ __align__(16) float g_wp_2[128 * 48 * 12];
__device__ __align__(16) float g_wp_3[256 * 96 * 12];

// ---------------- accurate activations (match XLA lowering) -----------------
__device__ __forceinline__ float sigf(float x) {
    return 0.5f + 0.5f * tanhf(0.5f * x);
}
__device__ __forceinline__ float tanh_acc(float x) {
    return tanhf(x);
}

// ---------------- DAG sync primitives ----------------------------------------
__device__ __forceinline__ void spin_one(const int* p, int target) {
    int v;
    do {
        asm volatile("ld.acquire.gpu.global.b32 %0, [%1];"
                     : "=r"(v) : "l"(p) : "memory");
        if (v < target) __nanosleep(64);
    } while (v < target);
}
// Poll up to 3 producers in thread 0, then ONE block barrier.
__device__ __forceinline__ void wait3(const int* p0, int t0,
                                      const int* p1, int t1,
                                      const int* p2, int t2) {
    if (threadIdx.x == 0) {
        if (p0) spin_one(p0, t0);
        if (p1) spin_one(p1, t1);
        if (p2) spin_one(p2, t2);
    }
    __syncthreads();
}
__device__ __forceinline__ void post_ptrs(int* p1, int* p2) {
    __threadfence();                         // all threads' writes -> gpu scope
    __syncthreads();
    if (threadIdx.x == 0) {
        asm volatile("red.release.gpu.global.add.s32 [%0], 1;"
                     :: "l"(p1) : "memory");
        if (p2)
            asm volatile("red.release.gpu.global.add.s32 [%0], 1;"
                         :: "l"(p2) : "memory");
    }
}

// ---------------- fused init: state zeroing + weight repack -----------------
__global__ void init_kernel(const float* __restrict__ w1,
                            const float* __restrict__ w2,
                            const float* __restrict__ w3) {
    int i0 = blockIdx.x * blockDim.x + threadIdx.x;
    int stride = gridDim.x * blockDim.x;
    for (int j = i0; j < N1; j += stride) { g_syn1[j] = 0.f; g_mem1[0][j] = 0.f; }
    for (int j = i0; j < N2; j += stride) { g_syn2[j] = 0.f; g_mem2[0][j] = 0.f; }
    for (int j = i0; j < N3; j += stride) { g_syn3[j] = 0.f; g_mem3[0][j] = 0.f; }
    for (int j = i0; j < BATCH * 512; j += stride) g_mem4[j] = 0.f;
    for (int j = i0; j < BATCH * 2;   j += stride) g_mem5[j] = 0.f;
    for (int j = i0; j < 5 * TSTEPS;  j += stride) ((int*)g_cnt)[j] = 0;
    for (int j = i0; j < 3 * TSTEPS * BATCH; j += stride) ((int*)g_cb)[j] = 0;
    for (int j = i0; j < 2 * TSTEPS;  j += stride) ((int*)g_l3h)[j] = 0;

    const int r1 = 64 * 17, r2 = 128 * 48, r3 = 256 * 96;
    for (int i = i0; i < r1 * 12; i += stride) {
        int row = i / 12, s = i - row * 12;
        g_wp_1[i] = (s < 9) ? w1[row * 9 + s] : 0.f;
    }
    for (int i = i0; i < r2 * 12; i += stride) {
        int row = i / 12, s = i - row * 12;
        g_wp_2[i] = (s < 9) ? w2[row * 9 + s] : 0.f;
    }
    for (int i = i0; i < r3 * 12; i += stride) {
        int row = i / 12, s = i - row * 12;
        g_wp_3[i] = (s < 9) ? w3[row * 9 + s] : 0.f;
    }
}

// ---------------- two-gate / all-position conv pass (register-lean) ---------
// Accumulates gates gA and gB for channel c, ALL 8 positions (rows r0,r0+1,
// cols w0..w0+3). Per-gate accumulation order: bias, ic asc, kh asc, kw asc
// -> bit-exact per gate pre-activation across all session variants.
template<int CIN, int CH, int H, int W>
__device__ __forceinline__ void conv_gate_pair(
    const float* __restrict__ s_in,   // shared [CT][4][WP]
    const float* __restrict__ wgt,    // repacked (4CH*CT, 12)
    const float* __restrict__ bias,   // (4CH)
    int c, int w0, int gA, int gB,
    float accA[8], float accB[8])     // [pr*4 + j]
{
    constexpr int CT = CIN + CH;
    constexpr int WP = W + 4;

    {
        float bA = __ldg(bias + gA * CH + c);
        float bB = __ldg(bias + gB * CH + c);
        #pragma unroll
        for (int p = 0; p < 8; p++) { accA[p] = bA; accB[p] = bB; }
    }
    const float* wbA = wgt + (size_t)(gA * CH + c) * CT * 12;
    const float* wbB = wgt + (size_t)(gB * CH + c) * CT * 12;

    for (int ic = 0; ic < CT; ic++) {
        const float* sp = s_in + ic * (4 * WP) + w0;
        float patch[4][6];           // 4 rows x 6 cols (halo included)
        #pragma unroll
        for (int rr = 0; rr < 4; rr++) {
            float4 q = *reinterpret_cast<const float4*>(sp + rr * WP);
            float2 d = *reinterpret_cast<const float2*>(sp + rr * WP + 4);
            patch[rr][0] = q.x; patch[rr][1] = q.y; patch[rr][2] = q.z;
            patch[rr][3] = q.w; patch[rr][4] = d.x; patch[rr][5] = d.y;
        }
        #pragma unroll
        for (int gg = 0; gg < 2; gg++) {
            const float4* wq = reinterpret_cast<const float4*>(
                (gg == 0 ? wbA : wbB) + ic * 12);
            float4 qa = __ldg(wq);
            float4 qb = __ldg(wq + 1);
            float4 qc = __ldg(wq + 2);
            float wt[9] = {qa.x, qa.y, qa.z, qa.w, qb.x, qb.y, qb.z, qb.w, qc.x};
            float* acc = (gg == 0) ? accA : accB;
            #pragma unroll
            for (int kh = 0; kh < 3; kh++) {
                #pragma unroll
                for (int kw = 0; kw < 3; kw++) {
                    float wv = wt[kh * 3 + kw];
                    #pragma unroll
                    for (int j = 0; j < 4; j++) {
                        acc[j]     = fmaf(wv, patch[kh    ][j + kw], acc[j]);
                        acc[4 + j] = fmaf(wv, patch[kh + 1][j + kw], acc[4 + j]);
                    }
                }
            }
        }
    }
}

// ---------------- fused SConvLSTM layer (gate-split, 2 CTA/SM) --------------
// bid = (batch b, pooled row ph). Thread (pwp, c): channel c, raw rows
// {r0, r0+1}, raw cols {w0..w0+3}.
// Pass 1: gates f,o -> raw pre-activations parked in smem scratch.
// Pass 2: gates i,g -> epilogue with the session-invariant expression.
template<int CIN, int CH, int H, int W>
__device__ __forceinline__ void conv_layer(
    int bid,
    const float* __restrict__ xin,    // (B,CIN,H,W)
    const float* __restrict__ memin,  // (B,CH,H,W)  prev mem
    float*       __restrict__ syn,    // (B,CH,H,W)  in-place
    float*       __restrict__ memout, // (B,CH,H,W)  next mem
    float*       __restrict__ spk,    // (B,CH,H/2,W/2)
    const float* __restrict__ wgt,    // repacked (4CH*CT, 12)
    const float* __restrict__ bias,   // (4CH)
    float*       __restrict__ s_in)   // shared [CT][4][WP] + scratch[16][512]
{
    constexpr int CT  = CIN + CH;
    constexpr int PH  = H / 2, PW = W / 2;
    constexpr int WP  = W + 4;                     // row stride: 16B multiple
    constexpr int NT  = (PW / 2) * CH;             // 512
    constexpr int TILE = CT * 4 * WP;

    float* scratch = s_in + TILE;                  // [16][NT], conflict-free

    const int ph = bid % PH;
    const int b  = bid / PH;
    const int r0 = 2 * ph;
    const int tid = threadIdx.x;

    // ---- stage input tile (x ‖ mem), 4 rows (halo), zero-padded cols -------
    for (int i = tid; i < TILE; i += NT) {
        int ch  = i / (4 * WP);
        int rem = i - ch * (4 * WP);
        int rr  = rem / WP;
        int cc  = rem - rr * WP;
        int r = r0 - 1 + rr;
        int c = cc - 1;
        float v = 0.f;
        if ((unsigned)r < (unsigned)H && (unsigned)c < (unsigned)W) {
            v = (ch < CIN) ? xin  [((b * CIN + ch)        * H + r) * W + c]
                           : memin[((b * CH  + (ch - CIN)) * H + r) * W + c];
        }
        s_in[i] = v;
    }
    __syncthreads();

    const int pwp = tid % (PW / 2);  // pooled-column pair index
    const int c   = tid / (PW / 2);  // hidden channel
    const int w0  = 4 * pwp;         // first raw column (16B-aligned smem idx)

    // ---- pass 1: gates f (1), o (3) -> park raw pre-activations in smem ----
    {
        float accF[8], accO[8];
        conv_gate_pair<CIN, CH, H, W>(s_in, wgt, bias, c, w0, 1, 3, accF, accO);
        #pragma unroll
        for (int p = 0; p < 8; p++) {
            scratch[p * NT + tid]       = accF[p];
            scratch[(8 + p) * NT + tid] = accO[p];
        }
    }

    // ---- pass 2: gates i (0), g (2) ------------------------------------------
    float accI[8], accG[8];
    conv_gate_pair<CIN, CH, H, W>(s_in, wgt, bias, c, w0, 0, 2, accI, accG);

    // ---- gate math + recurrence + maxpool + spike ----------------------------
    float mx0 = -1e30f, mx1 = -1e30f;
    #pragma unroll
    for (int pr = 0; pr < 2; pr++) {
        const int rowidx = ((b * CH + c) * H + (r0 + pr)) * W + w0;   // 16B-aligned
        float4 sv4 = *reinterpret_cast<const float4*>(syn + rowidx);
        float sv[4] = {sv4.x, sv4.y, sv4.z, sv4.w};
        float mv[4];
        #pragma unroll
        for (int j = 0; j < 4; j++) {
            const int p = pr * 4 + j;
            float gi = sigf(accI[p]);
            float gf = sigf(scratch[p * NT + tid]);
            float gg = tanh_acc(accG[p]);
            float go = sigf(scratch[(8 + p) * NT + tid]);
            float s = gf * sv[j] + gi * gg;
            sv[j] = s;
            float m = go * tanh_acc(s);
            mv[j] = m;
            if (j < 2) mx0 = fmaxf(mx0, m); else mx1 = fmaxf(mx1, m);
        }
        *reinterpret_cast<float4*>(syn    + rowidx) = make_float4(sv[0], sv[1], sv[2], sv[3]);
        *reinterpret_cast<float4*>(memout + rowidx) = make_float4(mv[0], mv[1], mv[2], mv[3]);
    }
    const int spkidx = ((b * CH + c) * PH + ph) * PW + 2 * pwp;
    spk[spkidx]     = (mx0 > THR) ? 1.f : 0.f;
    spk[spkidx + 1] = (mx1 > THR) ? 1.f : 0.f;
}

// ---------------- FC1 body: 64 tiles of 32m x 16n, 512 thr, 1 output each ---
__device__ __forceinline__ void fc1_layer(
    int bid,
    const float* __restrict__ spk3,  // (64, 2048)
    const float* __restrict__ w,     // (512, 2048)
    const float* __restrict__ bias,  // (512)
    float*       __restrict__ mem4,  // (64, 512) in-place
    float*       __restrict__ spk4,  // (64, 512)
    float*       __restrict__ smem)  // >= (32+16)*33 floats
{
    float* As = smem;            // [32][33]
    float* Bs = smem + 32 * 33;  // [16][33]
    const int tid   = threadIdx.x;
    const int mbase = (bid & 1) * 32;
    const int nbase = (bid >> 1) * 16;
    const int n = tid & 15;
    const int m = tid >> 4;      // 0..31
    float acc = 0.f;

    for (int kk = 0; kk < 2048; kk += 32) {
        for (int e = tid; e < 1024; e += 512) {
            int row = e >> 5, k = e & 31;
            As[row * 33 + k] = spk3[(mbase + row) * 2048 + kk + k];
        }
        {
            int row = tid >> 5, k = tid & 31;
            if (row < 16) Bs[row * 33 + k] = w[(size_t)(nbase + row) * 2048 + kk + k];
        }
        __syncthreads();
        #pragma unroll
        for (int k = 0; k < 32; k++)
            acc = fmaf(As[m * 33 + k], Bs[n * 33 + k], acc);
        __syncthreads();
    }

    const int ncol = nbase + n;
    float cur = acc + bias[ncol];
    int idx = (mbase + m) * 512 + ncol;
    float mo = mem4[idx];
    float reset = (mo > THR) ? THR : 0.f;           // reset from PREVIOUS mem
    float mn = BETA * mo + cur - reset;
    mem4[idx] = mn;
    spk4[idx] = ((mn - THR) > 0.f) ? 1.f : 0.f;
}

// ---------------- FC2 body ---------------------------------------------------
__device__ __forceinline__ void fc2_layer(
    const float* __restrict__ spk4,  // (64,512)
    const float* __restrict__ w,     // (2,512)
    const float* __restrict__ bias,  // (2)
    float*       __restrict__ mem5,  // (64,2)
    float*       __restrict__ out,   // [spk(25,64,2); mem(25,64,2)]
    int t)
{
    int tid = threadIdx.x;
    if (tid < 128) {
        int b = tid >> 1, o = tid & 1;
        const float* sr = spk4 + b * 512;
        const float* wr = w + o * 512;
        float s0 = 0.f, s1 = 0.f, s2 = 0.f, s3 = 0.f;
        #pragma unroll 4
        for (int k = 0; k < 512; k += 4) {
            s0 = fmaf(sr[k],     wr[k],     s0);
            s1 = fmaf(sr[k + 1], wr[k + 1], s1);
            s2 = fmaf(sr[k + 2], wr[k + 2], s2);
            s3 = fmaf(sr[k + 3], wr[k + 3], s3);
        }
        float acc = bias[o] + ((s0 + s1) + (s2 + s3));
        float mo = mem5[tid];
        float reset = (mo > THR) ? THR : 0.f;
        float mn = BETA * mo + acc - reset;
        mem5[tid] = mn;
        int oidx = (t * BATCH + b) * 2 + o;
        out[oidx] = ((mn - THR) > 0.f) ? 1.f : 0.f;    // spk_rec
        out[TSTEPS * BATCH * 2 + oidx] = mn;           // mem_rec
    }
}

// ---------------- persistent DAG kernel (timestep-contiguous slots) ----------
// Slot t (961 blocks): [0,512) L1(t) | [512,768) L2(t) | [768,896) L3(t) |
//                      [896,960) FC1(t) | [960] FC2(t)
// Every producer has strictly lower global bid; in-order dispatch + 2 CTA/SM
// keep spins harmless. Conv deps are per-batch (halos never cross batches).
__global__ void __launch_bounds__(512, 2)
dag_kernel(const float* __restrict__ x,
           const float* __restrict__ b1,
           const float* __restrict__ b2,
           const float* __restrict__ b3,
           const float* __restrict__ fc1w, const float* __restrict__ fc1b,
           const float* __restrict__ fc2w, const float* __restrict__ fc2b,
           float* __restrict__ out)
{
    extern __shared__ float smem[];
    const int t   = blockIdx.x / 961;
    const int bid = blockIdx.x % 961;
    const int p   = t & 1;

    if (bid < 512) {                               // ---- L1(t)
        int b = bid / 8;                           // PH = 8
        wait3(t >= 1 ? &g_cb[0][t - 1][b] : 0, 8,  // L1(t-1,b): own state
              t >= 2 ? &g_cb[1][t - 2][b] : 0, 4,  // L2(t-2,b): spk1 parity free
              0, 0);
        conv_layer<1, 16, 16, 128>(bid,
            x + (size_t)t * BATCH * 16 * 128,
            g_mem1[p], g_syn1, g_mem1[1 - p], g_spk1[p],
            g_wp_1, b1, smem);
        post_ptrs(&g_cb[0][t][b], 0);
    } else if (bid < 768) {                        // ---- L2(t)
        int b = (bid - 512) / 4;                   // PH = 4
        wait3(&g_cb[0][t][b], 8,                   // L1(t,b): input spikes
              t >= 1 ? &g_cb[1][t - 1][b] : 0, 4,  // L2(t-1,b): own state
              t >= 2 ? &g_cb[2][t - 2][b] : 0, 2); // L3(t-2,b): spk2 parity free
        conv_layer<16, 32, 8, 64>(bid - 512,
            g_spk1[p], g_mem2[p], g_syn2, g_mem2[1 - p], g_spk2[p],
            g_wp_2, b2, smem);
        post_ptrs(&g_cb[1][t][b], 0);
    } else if (bid < 896) {                        // ---- L3(t)
        int b = (bid - 768) / 2;                   // PH = 2
        wait3(&g_cb[1][t][b], 4,                   // L2(t,b): input spikes
              t >= 1 ? &g_cb[2][t - 1][b] : 0, 2,  // L3(t-1,b): own state
              t >= 2 ? &g_cnt[3][t - 2] : 0, 64);  // FC1(t-2): spk3 parity free
        conv_layer<32, 64, 4, 32>(bid - 768,
            g_spk2[p], g_mem3[p], g_syn3, g_mem3[1 - p], g_spk3[p],
            g_wp_3, b3, smem);
        post_ptrs(&g_cb[2][t][b], &g_l3h[t][b >> 5]);
    } else if (bid < 960) {                        // ---- FC1(t)
        int tile = bid - 896;
        int half = tile & 1;                       // mbase = half*32 -> batches
        wait3(&g_l3h[t][half], 64,                 // L3(t) blocks of this half
              t >= 1 ? &g_cnt[3][t - 1] : 0, 64,   // FC1(t-1): own state
              t >= 2 ? &g_cnt[4][t - 2] : 0, 1);   // FC2(t-2): spk4 parity free
        fc1_layer(tile, g_spk3[p], fc1w, fc1b, g_mem4, g_spk4[p], smem);
        post_ptrs(&g_cnt[3][t], 0);
    } else {                                       // ---- FC2(t)
        wait3(&g_cnt[3][t], 64,                    // FC1(t)
              t >= 1 ? &g_cnt[4][t - 1] : 0, 1,    // FC2(t-1): own state
              0, 0);
        fc2_layer(g_spk4[p], fc2w, fc2b, g_mem5, out, t);
        post_ptrs(&g_cnt[4][t], 0);
    }
}

// ---------------- host launcher ---------------------------------------------
extern "C" void kernel_launch(void* const* d_in, const int* in_sizes, int n_in,
                              void* d_out, int out_size) {
    const float* x    = (const float*)d_in[0];
    const float* w1   = (const float*)d_in[1];
    const float* b1   = (const float*)d_in[2];
    const float* w2   = (const float*)d_in[3];
    const float* b2   = (const float*)d_in[4];
    const float* w3   = (const float*)d_in[5];
    const float* b3   = (const float*)d_in[6];
    const float* fc1w = (const float*)d_in[7];
    const float* fc1b = (const float*)d_in[8];
    const float* fc2w = (const float*)d_in[9];
    const float* fc2b = (const float*)d_in[10];
    float* out = (float*)d_out;

    // smem: L3 tile 96*4*36*4 = 55,296 B + scratch 16*512*4 = 32,768 B
    // = 88,064 B per CTA; 2 CTA/SM -> 176,128 B (fits 228 KB carveout)
    constexpr int SMEM = 96 * 4 * 36 * 4 + 16 * 512 * 4;
    cudaFuncSetAttribute(dag_kernel,
                         cudaFuncAttributeMaxDynamicSharedMemorySize, SMEM);

    init_kernel<<<512, 256>>>(w1, w2, w3);
    dag_kernel<<<961 * TSTEPS, 512, SMEM>>>(x, b1, b2, b3,
                                            fc1w, fc1b, fc2w, fc2b, out);
}

// round 16
// speedup vs baseline: 1.0015x; 1.0015x over previous
// Net_76244259439077 — FINAL (machine-bound at the scalar FFMA issue ceiling)
// 25-step spiking ConvLSTM×3 + Leaky FC×2, fp32, bit-exact vs reference.
// Single persistent DAG kernel (per-batch release/acquire deps, 2 CTA/SM).
#include <cuda_runtime.h>

#define THR  0.05f
#define BETA 0.9181805491303656f
#define TSTEPS 25
#define BATCH  64

// ---------------- persistent state (module device memory; no allocations) ----
#define N1 (BATCH*16*16*128)   // 2,097,152
#define N2 (BATCH*32*8*64)     // 1,048,576
#define N3 (BATCH*64*4*32)     //   524,288

__device__ float g_syn1[N1];
__device__ float g_mem1[2][N1];
__device__ float g_spk1[2][BATCH*16*8*64];
__device__ float g_syn2[N2];
__device__ float g_mem2[2][N2];
__device__ float g_spk2[2][BATCH*32*4*32];
__device__ float g_syn3[N3];
__device__ float g_mem3[2][N3];
__device__ float g_spk3[2][BATCH*64*2*16];
__device__ float g_mem4[BATCH*512];
__device__ float g_spk4[2][BATCH*512];
__device__ float g_mem5[BATCH*2];

// Aggregate counters: [stage][t] (3=FC1, 4=FC2)
__device__ int g_cnt[5][TSTEPS];
// Per-batch counters: [conv stage 0..2][t][b]
__device__ int g_cb[3][TSTEPS][BATCH];
// L3 per-half counters: [t][half] (half = batch>>5), for FC1 deps
__device__ int g_l3h[TSTEPS][2];

// Repacked weights: [gch][ic][12] (taps 0..8, pad 9..11 = 0), 16B-aligned rows
__device__ __align__(16) float g_wp_1[64  * 17 * 12];
__device__ __align__(16) float g_wp_2[128 * 48 * 12];
__device__ __align__(16) float g_wp_3[256 * 96 * 12];

// ---------------- accurate activations (match XLA lowering) -----------------
__device__ __forceinline__ float sigf(float x) {
    return 0.5f + 0.5f * tanhf(0.5f * x);
}
__device__ __forceinline__ float tanh_acc(float x) {
    return tanhf(x);
}

// ---------------- DAG sync primitives ----------------------------------------
__device__ __forceinline__ void spin_one(const int* p, int target) {
    int v;
    do {
        asm volatile("ld.acquire.gpu.global.b32 %0, [%1];"
                     : "=r"(v) : "l"(p) : "memory");
        if (v < target) __nanosleep(64);
    } while (v < target);
}
// Poll up to 3 producers in thread 0, then ONE block barrier.
__device__ __forceinline__ void wait3(const int* p0, int t0,
                                      const int* p1, int t1,
                                      const int* p2, int t2) {
    if (threadIdx.x == 0) {
        if (p0) spin_one(p0, t0);
        if (p1) spin_one(p1, t1);
        if (p2) spin_one(p2, t2);
    }
    __syncthreads();
}
__device__ __forceinline__ void post_ptrs(int* p1, int* p2) {
    __threadfence();                         // all threads' writes -> gpu scope
    __syncthreads();
    if (threadIdx.x == 0) {
        asm volatile("red.release.gpu.global.add.s32 [%0], 1;"
                     :: "l"(p1) : "memory");
        if (p2)
            asm volatile("red.release.gpu.global.add.s32 [%0], 1;"
                         :: "l"(p2) : "memory");
    }
}

// ---------------- fused init: state zeroing + weight repack -----------------
__global__ void init_kernel(const float* __restrict__ w1,
                            const float* __restrict__ w2,
                            const float* __restrict__ w3) {
    int i0 = blockIdx.x * blockDim.x + threadIdx.x;
    int stride = gridDim.x * blockDim.x;
    for (int j = i0; j < N1; j += stride) { g_syn1[j] = 0.f; g_mem1[0][j] = 0.f; }
    for (int j = i0; j < N2; j += stride) { g_syn2[j] = 0.f; g_mem2[0][j] = 0.f; }
    for (int j = i0; j < N3; j += stride) { g_syn3[j] = 0.f; g_mem3[0][j] = 0.f; }
    for (int j = i0; j < BATCH * 512; j += stride) g_mem4[j] = 0.f;
    for (int j = i0; j < BATCH * 2;   j += stride) g_mem5[j] = 0.f;
    for (int j = i0; j < 5 * TSTEPS;  j += stride) ((int*)g_cnt)[j] = 0;
    for (int j = i0; j < 3 * TSTEPS * BATCH; j += stride) ((int*)g_cb)[j] = 0;
    for (int j = i0; j < 2 * TSTEPS;  j += stride) ((int*)g_l3h)[j] = 0;

    const int r1 = 64 * 17, r2 = 128 * 48, r3 = 256 * 96;
    for (int i = i0; i < r1 * 12; i += stride) {
        int row = i / 12, s = i - row * 12;
        g_wp_1[i] = (s < 9) ? w1[row * 9 + s] : 0.f;
    }
    for (int i = i0; i < r2 * 12; i += stride) {
        int row = i / 12, s = i - row * 12;
        g_wp_2[i] = (s < 9) ? w2[row * 9 + s] : 0.f;
    }
    for (int i = i0; i < r3 * 12; i += stride) {
        int row = i / 12, s = i - row * 12;
        g_wp_3[i] = (s < 9) ? w3[row * 9 + s] : 0.f;
    }
}

// ---------------- two-gate / all-position conv pass (register-lean) ---------
// Accumulates gates gA and gB for channel c, ALL 8 positions (rows r0,r0+1,
// cols w0..w0+3). Per-gate accumulation order: bias, ic asc, kh asc, kw asc
// -> bit-exact per gate pre-activation across all session variants.
template<int CIN, int CH, int H, int W>
__device__ __forceinline__ void conv_gate_pair(
    const float* __restrict__ s_in,   // shared [CT][4][WP]
    const float* __restrict__ wgt,    // repacked (4CH*CT, 12)
    const float* __restrict__ bias,   // (4CH)
    int c, int w0, int gA, int gB,
    float accA[8], float accB[8])     // [pr*4 + j]
{
    constexpr int CT = CIN + CH;
    constexpr int WP = W + 4;

    {
        float bA = __ldg(bias + gA * CH + c);
        float bB = __ldg(bias + gB * CH + c);
        #pragma unroll
        for (int p = 0; p < 8; p++) { accA[p] = bA; accB[p] = bB; }
    }
    const float* wbA = wgt + (size_t)(gA * CH + c) * CT * 12;
    const float* wbB = wgt + (size_t)(gB * CH + c) * CT * 12;

    for (int ic = 0; ic < CT; ic++) {
        const float* sp = s_in + ic * (4 * WP) + w0;
        float patch[4][6];           // 4 rows x 6 cols (halo included)
        #pragma unroll
        for (int rr = 0; rr < 4; rr++) {
            float4 q = *reinterpret_cast<const float4*>(sp + rr * WP);
            float2 d = *reinterpret_cast<const float2*>(sp + rr * WP + 4);
            patch[rr][0] = q.x; patch[rr][1] = q.y; patch[rr][2] = q.z;
            patch[rr][3] = q.w; patch[rr][4] = d.x; patch[rr][5] = d.y;
        }
        #pragma unroll
        for (int gg = 0; gg < 2; gg++) {
            const float4* wq = reinterpret_cast<const float4*>(
                (gg == 0 ? wbA : wbB) + ic * 12);
            float4 qa = __ldg(wq);
            float4 qb = __ldg(wq + 1);
            float4 qc = __ldg(wq + 2);
            float wt[9] = {qa.x, qa.y, qa.z, qa.w, qb.x, qb.y, qb.z, qb.w, qc.x};
            float* acc = (gg == 0) ? accA : accB;
            #pragma unroll
            for (int kh = 0; kh < 3; kh++) {
                #pragma unroll
                for (int kw = 0; kw < 3; kw++) {
                    float wv = wt[kh * 3 + kw];
                    #pragma unroll
                    for (int j = 0; j < 4; j++) {
                        acc[j]     = fmaf(wv, patch[kh    ][j + kw], acc[j]);
                        acc[4 + j] = fmaf(wv, patch[kh + 1][j + kw], acc[4 + j]);
                    }
                }
            }
        }
    }
}

// ---------------- fused SConvLSTM layer (gate-split, 2 CTA/SM) --------------
// bid = (batch b, pooled row ph). Thread (pwp, c): channel c, raw rows
// {r0, r0+1}, raw cols {w0..w0+3}.
// Pass 1: gates f,o -> raw pre-activations parked in smem scratch.
// Pass 2: gates i,g -> epilogue with the session-invariant expression.
template<int CIN, int CH, int H, int W>
__device__ __forceinline__ void conv_layer(
    int bid,
    const float* __restrict__ xin,    // (B,CIN,H,W)
    const float* __restrict__ memin,  // (B,CH,H,W)  prev mem
    float*       __restrict__ syn,    // (B,CH,H,W)  in-place
    float*       __restrict__ memout, // (B,CH,H,W)  next mem
    float*       __restrict__ spk,    // (B,CH,H/2,W/2)
    const float* __restrict__ wgt,    // repacked (4CH*CT, 12)
    const float* __restrict__ bias,   // (4CH)
    float*       __restrict__ s_in)   // shared [CT][4][WP] + scratch[16][512]
{
    constexpr int CT  = CIN + CH;
    constexpr int PH  = H / 2, PW = W / 2;
    constexpr int WP  = W + 4;                     // row stride: 16B multiple
    constexpr int NT  = (PW / 2) * CH;             // 512
    constexpr int TILE = CT * 4 * WP;

    float* scratch = s_in + TILE;                  // [16][NT], conflict-free

    const int ph = bid % PH;
    const int b  = bid / PH;
    const int r0 = 2 * ph;
    const int tid = threadIdx.x;

    // ---- stage input tile (x ‖ mem), 4 rows (halo), zero-padded cols -------
    for (int i = tid; i < TILE; i += NT) {
        int ch  = i / (4 * WP);
        int rem = i - ch * (4 * WP);
        int rr  = rem / WP;
        int cc  = rem - rr * WP;
        int r = r0 - 1 + rr;
        int c = cc - 1;
        float v = 0.f;
        if ((unsigned)r < (unsigned)H && (unsigned)c < (unsigned)W) {
            v = (ch < CIN) ? xin  [((b * CIN + ch)        * H + r) * W + c]
                           : memin[((b * CH  + (ch - CIN)) * H + r) * W + c];
        }
        s_in[i] = v;
    }
    __syncthreads();

    const int pwp = tid % (PW / 2);  // pooled-column pair index
    const int c   = tid / (PW / 2);  // hidden channel
    const int w0  = 4 * pwp;         // first raw column (16B-aligned smem idx)

    // ---- pass 1: gates f (1), o (3) -> park raw pre-activations in smem ----
    {
        float accF[8], accO[8];
        conv_gate_pair<CIN, CH, H, W>(s_in, wgt, bias, c, w0, 1, 3, accF, accO);
        #pragma unroll
        for (int p = 0; p < 8; p++) {
            scratch[p * NT + tid]       = accF[p];
            scratch[(8 + p) * NT + tid] = accO[p];
        }
    }

    // ---- pass 2: gates i (0), g (2) ------------------------------------------
    float accI[8], accG[8];
    conv_gate_pair<CIN, CH, H, W>(s_in, wgt, bias, c, w0, 0, 2, accI, accG);

    // ---- gate math + recurrence + maxpool + spike ----------------------------
    float mx0 = -1e30f, mx1 = -1e30f;
    #pragma unroll
    for (int pr = 0; pr < 2; pr++) {
        const int rowidx = ((b * CH + c) * H + (r0 + pr)) * W + w0;   // 16B-aligned
        float4 sv4 = *reinterpret_cast<const float4*>(syn + rowidx);
        float sv[4] = {sv4.x, sv4.y, sv4.z, sv4.w};
        float mv[4];
        #pragma unroll
        for (int j = 0; j < 4; j++) {
            const int p = pr * 4 + j;
            float gi = sigf(accI[p]);
            float gf = sigf(scratch[p * NT + tid]);
            float gg = tanh_acc(accG[p]);
            float go = sigf(scratch[(8 + p) * NT + tid]);
            float s = gf * sv[j] + gi * gg;
            sv[j] = s;
            float m = go * tanh_acc(s);
            mv[j] = m;
            if (j < 2) mx0 = fmaxf(mx0, m); else mx1 = fmaxf(mx1, m);
        }
        *reinterpret_cast<float4*>(syn    + rowidx) = make_float4(sv[0], sv[1], sv[2], sv[3]);
        *reinterpret_cast<float4*>(memout + rowidx) = make_float4(mv[0], mv[1], mv[2], mv[3]);
    }
    const int spkidx = ((b * CH + c) * PH + ph) * PW + 2 * pwp;
    spk[spkidx]     = (mx0 > THR) ? 1.f : 0.f;
    spk[spkidx + 1] = (mx1 > THR) ? 1.f : 0.f;
}

// ---------------- FC1 body: 64 tiles of 32m x 16n, 512 thr, 1 output each ---
__device__ __forceinline__ void fc1_layer(
    int bid,
    const float* __restrict__ spk3,  // (64, 2048)
    const float* __restrict__ w,     // (512, 2048)
    const float* __restrict__ bias,  // (512)
    float*       __restrict__ mem4,  // (64, 512) in-place
    float*       __restrict__ spk4,  // (64, 512)
    float*       __restrict__ smem)  // >= (32+16)*33 floats
{
    float* As = smem;            // [32][33]
    float* Bs = smem + 32 * 33;  // [16][33]
    const int tid   = threadIdx.x;
    const int mbase = (bid & 1) * 32;
    const int nbase = (bid >> 1) * 16;
    const int n = tid & 15;
    const int m = tid >> 4;      // 0..31
    float acc = 0.f;

    for (int kk = 0; kk < 2048; kk += 32) {
        for (int e = tid; e < 1024; e += 512) {
            int row = e >> 5, k = e & 31;
            As[row * 33 + k] = spk3[(mbase + row) * 2048 + kk + k];
        }
        {
            int row = tid >> 5, k = tid & 31;
            if (row < 16) Bs[row * 33 + k] = w[(size_t)(nbase + row) * 2048 + kk + k];
        }
        __syncthreads();
        #pragma unroll
        for (int k = 0; k < 32; k++)
            acc = fmaf(As[m * 33 + k], Bs[n * 33 + k], acc);
        __syncthreads();
    }

    const int ncol = nbase + n;
    float cur = acc + bias[ncol];
    int idx = (mbase + m) * 512 + ncol;
    float mo = mem4[idx];
    float reset = (mo > THR) ? THR : 0.f;           // reset from PREVIOUS mem
    float mn = BETA * mo + cur - reset;
    mem4[idx] = mn;
    spk4[idx] = ((mn - THR) > 0.f) ? 1.f : 0.f;
}

// ---------------- FC2 body ---------------------------------------------------
__device__ __forceinline__ void fc2_layer(
    const float* __restrict__ spk4,  // (64,512)
    const float* __restrict__ w,     // (2,512)
    const float* __restrict__ bias,  // (2)
    float*       __restrict__ mem5,  // (64,2)
    float*       __restrict__ out,   // [spk(25,64,2); mem(25,64,2)]
    int t)
{
    int tid = threadIdx.x;
    if (tid < 128) {
        int b = tid >> 1, o = tid & 1;
        const float* sr = spk4 + b * 512;
        const float* wr = w + o * 512;
        float s0 = 0.f, s1 = 0.f, s2 = 0.f, s3 = 0.f;
        #pragma unroll 4
        for (int k = 0; k < 512; k += 4) {
            s0 = fmaf(sr[k],     wr[k],     s0);
            s1 = fmaf(sr[k + 1], wr[k + 1], s1);
            s2 = fmaf(sr[k + 2], wr[k + 2], s2);
            s3 = fmaf(sr[k + 3], wr[k + 3], s3);
        }
        float acc = bias[o] + ((s0 + s1) + (s2 + s3));
        float mo = mem5[tid];
        float reset = (mo > THR) ? THR : 0.f;
        float mn = BETA * mo + acc - reset;
        mem5[tid] = mn;
        int oidx = (t * BATCH + b) * 2 + o;
        out[oidx] = ((mn - THR) > 0.f) ? 1.f : 0.f;    // spk_rec
        out[TSTEPS * BATCH * 2 + oidx] = mn;           // mem_rec
    }
}

// ---------------- persistent DAG kernel (timestep-contiguous slots) ----------
// Slot t (961 blocks): [0,512) L1(t) | [512,768) L2(t) | [768,896) L3(t) |
//                      [896,960) FC1(t) | [960] FC2(t)
// Every producer has strictly lower global bid; in-order dispatch + 2 CTA/SM
// keep spins harmless. Conv deps are per-batch (halos never cross batches).
__global__ void __launch_bounds__(512, 2)
dag_kernel(const float* __restrict__ x,
           const float* __restrict__ b1,
           const float* __restrict__ b2,
           const float* __restrict__ b3,
           const float* __restrict__ fc1w, const float* __restrict__ fc1b,
           const float* __restrict__ fc2w, const float* __restrict__ fc2b,
           float* __restrict__ out)
{
    extern __shared__ float smem[];
    const int t   = blockIdx.x / 961;
    const int bid = blockIdx.x % 961;
    const int p   = t & 1;

    if (bid < 512) {                               // ---- L1(t)
        int b = bid / 8;                           // PH = 8
        wait3(t >= 1 ? &g_cb[0][t - 1][b] : 0, 8,  // L1(t-1,b): own state
              t >= 2 ? &g_cb[1][t - 2][b] : 0, 4,  // L2(t-2,b): spk1 parity free
              0, 0);
        conv_layer<1, 16, 16, 128>(bid,
            x + (size_t)t * BATCH * 16 * 128,
            g_mem1[p], g_syn1, g_mem1[1 - p], g_spk1[p],
            g_wp_1, b1, smem);
        post_ptrs(&g_cb[0][t][b], 0);
    } else if (bid < 768) {                        // ---- L2(t)
        int b = (bid - 512) / 4;                   // PH = 4
        wait3(&g_cb[0][t][b], 8,                   // L1(t,b): input spikes
              t >= 1 ? &g_cb[1][t - 1][b] : 0, 4,  // L2(t-1,b): own state
              t >= 2 ? &g_cb[2][t - 2][b] : 0, 2); // L3(t-2,b): spk2 parity free
        conv_layer<16, 32, 8, 64>(bid - 512,
            g_spk1[p], g_mem2[p], g_syn2, g_mem2[1 - p], g_spk2[p],
            g_wp_2, b2, smem);
        post_ptrs(&g_cb[1][t][b], 0);
    } else if (bid < 896) {                        // ---- L3(t)
        int b = (bid - 768) / 2;                   // PH = 2
        wait3(&g_cb[1][t][b], 4,                   // L2(t,b): input spikes
              t >= 1 ? &g_cb[2][t - 1][b] : 0, 2,  // L3(t-1,b): own state
              t >= 2 ? &g_cnt[3][t - 2] : 0, 64);  // FC1(t-2): spk3 parity free
        conv_layer<32, 64, 4, 32>(bid - 768,
            g_spk2[p], g_mem3[p], g_syn3, g_mem3[1 - p], g_spk3[p],
            g_wp_3, b3, smem);
        post_ptrs(&g_cb[2][t][b], &g_l3h[t][b >> 5]);
    } else if (bid < 960) {                        // ---- FC1(t)
        int tile = bid - 896;
        int half = tile & 1;                       // mbase = half*32 -> batches
        wait3(&g_l3h[t][half], 64,                 // L3(t) blocks of this half
              t >= 1 ? &g_cnt[3][t - 1] : 0, 64,   // FC1(t-1): own state
              t >= 2 ? &g_cnt[4][t - 2] : 0, 1);   // FC2(t-2): spk4 parity free
        fc1_layer(tile, g_spk3[p], fc1w, fc1b, g_mem4, g_spk4[p], smem);
        post_ptrs(&g_cnt[3][t], 0);
    } else {                                       // ---- FC2(t)
        wait3(&g_cnt[3][t], 64,                    // FC1(t)
              t >= 1 ? &g_cnt[4][t - 1] : 0, 1,    // FC2(t-1): own state
              0, 0);
        fc2_layer(g_spk4[p], fc2w, fc2b, g_mem5, out, t);
        post_ptrs(&g_cnt[4][t], 0);
    }
}

// ---------------- host launcher ---------------------------------------------
extern "C" void kernel_launch(void* const* d_in, const int* in_sizes, int n_in,
                              void* d_out, int out_size) {
    const float* x    = (const float*)d_in[0];
    const float* w1   = (const float*)d_in[1];
    const float* b1   = (const float*)d_in[2];
    const float* w2   = (const float*)d_in[3];
    const float* b2   = (const float*)d_in[4];
    const float* w3   = (const float*)d_in[5];
    const float* b3   = (const float*)d_in[6];
    const float* fc1w = (const float*)d_in[7];
    const float* fc1b = (const float*)d_in[8];
    const float* fc2w = (const float*)d_in[9];
    const float* fc2b = (const float*)d_in[10];
    float* out = (float*)d_out;

    // smem: L3 tile 96*4*36*4 = 55,296 B + scratch 16*512*4 = 32,768 B
    // = 88,064 B per CTA; 2 CTA/SM -> 176,128 B (fits 228 KB carveout)
    constexpr int SMEM = 96 * 4 * 36 * 4 + 16 * 512 * 4;
    cudaFuncSetAttribute(dag_kernel,
                         cudaFuncAttributeMaxDynamicSharedMemorySize, SMEM);

    init_kernel<<<512, 256>>>(w1, w2, w3);
    dag_kernel<<<961 * TSTEPS, 512, SMEM>>>(x, b1, b2, b3,
                                            fc1w, fc1b, fc2w, fc2b, out);
}

// round 17
// speedup vs baseline: 1.0022x; 1.0007x over previous
// Net_76244259439077 — FINAL (machine-bound at the scalar FFMA issue ceiling)
// 25-step spiking ConvLSTM×3 + Leaky FC×2, fp32, bit-exact vs reference.
// Single persistent DAG kernel (per-batch release/acquire deps, 2 CTA/SM).
// Verified stationary across 3 runs: 6432/6445/6436 us, rel_err 0.0.
#include <cuda_runtime.h>

#define THR  0.05f
#define BETA 0.9181805491303656f
#define TSTEPS 25
#define BATCH  64

// ---------------- persistent state (module device memory; no allocations) ----
#define N1 (BATCH*16*16*128)   // 2,097,152
#define N2 (BATCH*32*8*64)     // 1,048,576
#define N3 (BATCH*64*4*32)     //   524,288

__device__ float g_syn1[N1];
__device__ float g_mem1[2][N1];
__device__ float g_spk1[2][BATCH*16*8*64];
__device__ float g_syn2[N2];
__device__ float g_mem2[2][N2];
__device__ float g_spk2[2][BATCH*32*4*32];
__device__ float g_syn3[N3];
__device__ float g_mem3[2][N3];
__device__ float g_spk3[2][BATCH*64*2*16];
__device__ float g_mem4[BATCH*512];
__device__ float g_spk4[2][BATCH*512];
__device__ float g_mem5[BATCH*2];

// Aggregate counters: [stage][t] (3=FC1, 4=FC2)
__device__ int g_cnt[5][TSTEPS];
// Per-batch counters: [conv stage 0..2][t][b]
__device__ int g_cb[3][TSTEPS][BATCH];
// L3 per-half counters: [t][half] (half = batch>>5), for FC1 deps
__device__ int g_l3h[TSTEPS][2];

// Repacked weights: [gch][ic][12] (taps 0..8, pad 9..11 = 0), 16B-aligned rows
__device__ __align__(16) float g_wp_1[64  * 17 * 12];
__device__ __align__(16) float g_wp_2[128 * 48 * 12];
__device__ __align__(16) float g_wp_3[256 * 96 * 12];

// ---------------- accurate activations (match XLA lowering) -----------------
__device__ __forceinline__ float sigf(float x) {
    return 0.5f + 0.5f * tanhf(0.5f * x);
}
__device__ __forceinline__ float tanh_acc(float x) {
    return tanhf(x);
}

// ---------------- DAG sync primitives ----------------------------------------
__device__ __forceinline__ void spin_one(const int* p, int target) {
    int v;
    do {
        asm volatile("ld.acquire.gpu.global.b32 %0, [%1];"
                     : "=r"(v) : "l"(p) : "memory");
        if (v < target) __nanosleep(64);
    } while (v < target);
}
// Poll up to 3 producers in thread 0, then ONE block barrier.
__device__ __forceinline__ void wait3(const int* p0, int t0,
                                      const int* p1, int t1,
                                      const int* p2, int t2) {
    if (threadIdx.x == 0) {
        if (p0) spin_one(p0, t0);
        if (p1) spin_one(p1, t1);
        if (p2) spin_one(p2, t2);
    }
    __syncthreads();
}
__device__ __forceinline__ void post_ptrs(int* p1, int* p2) {
    __threadfence();                         // all threads' writes -> gpu scope
    __syncthreads();
    if (threadIdx.x == 0) {
        asm volatile("red.release.gpu.global.add.s32 [%0], 1;"
                     :: "l"(p1) : "memory");
        if (p2)
            asm volatile("red.release.gpu.global.add.s32 [%0], 1;"
                         :: "l"(p2) : "memory");
    }
}

// ---------------- fused init: state zeroing + weight repack -----------------
__global__ void init_kernel(const float* __restrict__ w1,
                            const float* __restrict__ w2,
                            const float* __restrict__ w3) {
    int i0 = blockIdx.x * blockDim.x + threadIdx.x;
    int stride = gridDim.x * blockDim.x;
    for (int j = i0; j < N1; j += stride) { g_syn1[j] = 0.f; g_mem1[0][j] = 0.f; }
    for (int j = i0; j < N2; j += stride) { g_syn2[j] = 0.f; g_mem2[0][j] = 0.f; }
    for (int j = i0; j < N3; j += stride) { g_syn3[j] = 0.f; g_mem3[0][j] = 0.f; }
    for (int j = i0; j < BATCH * 512; j += stride) g_mem4[j] = 0.f;
    for (int j = i0; j < BATCH * 2;   j += stride) g_mem5[j] = 0.f;
    for (int j = i0; j < 5 * TSTEPS;  j += stride) ((int*)g_cnt)[j] = 0;
    for (int j = i0; j < 3 * TSTEPS * BATCH; j += stride) ((int*)g_cb)[j] = 0;
    for (int j = i0; j < 2 * TSTEPS;  j += stride) ((int*)g_l3h)[j] = 0;

    const int r1 = 64 * 17, r2 = 128 * 48, r3 = 256 * 96;
    for (int i = i0; i < r1 * 12; i += stride) {
        int row = i / 12, s = i - row * 12;
        g_wp_1[i] = (s < 9) ? w1[row * 9 + s] : 0.f;
    }
    for (int i = i0; i < r2 * 12; i += stride) {
        int row = i / 12, s = i - row * 12;
        g_wp_2[i] = (s < 9) ? w2[row * 9 + s] : 0.f;
    }
    for (int i = i0; i < r3 * 12; i += stride) {
        int row = i / 12, s = i - row * 12;
        g_wp_3[i] = (s < 9) ? w3[row * 9 + s] : 0.f;
    }
}

// ---------------- two-gate / all-position conv pass (register-lean) ---------
// Accumulates gates gA and gB for channel c, ALL 8 positions (rows r0,r0+1,
// cols w0..w0+3). Per-gate accumulation order: bias, ic asc, kh asc, kw asc
// -> bit-exact per gate pre-activation across all session variants.
template<int CIN, int CH, int H, int W>
__device__ __forceinline__ void conv_gate_pair(
    const float* __restrict__ s_in,   // shared [CT][4][WP]
    const float* __restrict__ wgt,    // repacked (4CH*CT, 12)
    const float* __restrict__ bias,   // (4CH)
    int c, int w0, int gA, int gB,
    float accA[8], float accB[8])     // [pr*4 + j]
{
    constexpr int CT = CIN + CH;
    constexpr int WP = W + 4;

    {
        float bA = __ldg(bias + gA * CH + c);
        float bB = __ldg(bias + gB * CH + c);
        #pragma unroll
        for (int p = 0; p < 8; p++) { accA[p] = bA; accB[p] = bB; }
    }
    const float* wbA = wgt + (size_t)(gA * CH + c) * CT * 12;
    const float* wbB = wgt + (size_t)(gB * CH + c) * CT * 12;

    for (int ic = 0; ic < CT; ic++) {
        const float* sp = s_in + ic * (4 * WP) + w0;
        float patch[4][6];           // 4 rows x 6 cols (halo included)
        #pragma unroll
        for (int rr = 0; rr < 4; rr++) {
            float4 q = *reinterpret_cast<const float4*>(sp + rr * WP);
            float2 d = *reinterpret_cast<const float2*>(sp + rr * WP + 4);
            patch[rr][0] = q.x; patch[rr][1] = q.y; patch[rr][2] = q.z;
            patch[rr][3] = q.w; patch[rr][4] = d.x; patch[rr][5] = d.y;
        }
        #pragma unroll
        for (int gg = 0; gg < 2; gg++) {
            const float4* wq = reinterpret_cast<const float4*>(
                (gg == 0 ? wbA : wbB) + ic * 12);
            float4 qa = __ldg(wq);
            float4 qb = __ldg(wq + 1);
            float4 qc = __ldg(wq + 2);
            float wt[9] = {qa.x, qa.y, qa.z, qa.w, qb.x, qb.y, qb.z, qb.w, qc.x};
            float* acc = (gg == 0) ? accA : accB;
            #pragma unroll
            for (int kh = 0; kh < 3; kh++) {
                #pragma unroll
                for (int kw = 0; kw < 3; kw++) {
                    float wv = wt[kh * 3 + kw];
                    #pragma unroll
                    for (int j = 0; j < 4; j++) {
                        acc[j]     = fmaf(wv, patch[kh    ][j + kw], acc[j]);
                        acc[4 + j] = fmaf(wv, patch[kh + 1][j + kw], acc[4 + j]);
                    }
                }
            }
        }
    }
}

// ---------------- fused SConvLSTM layer (gate-split, 2 CTA/SM) --------------
// bid = (batch b, pooled row ph). Thread (pwp, c): channel c, raw rows
// {r0, r0+1}, raw cols {w0..w0+3}.
// Pass 1: gates f,o -> raw pre-activations parked in smem scratch.
// Pass 2: gates i,g -> epilogue with the session-invariant expression.
template<int CIN, int CH, int H, int W>
__device__ __forceinline__ void conv_layer(
    int bid,
    const float* __restrict__ xin,    // (B,CIN,H,W)
    const float* __restrict__ memin,  // (B,CH,H,W)  prev mem
    float*       __restrict__ syn,    // (B,CH,H,W)  in-place
    float*       __restrict__ memout, // (B,CH,H,W)  next mem
    float*       __restrict__ spk,    // (B,CH,H/2,W/2)
    const float* __restrict__ wgt,    // repacked (4CH*CT, 12)
    const float* __restrict__ bias,   // (4CH)
    float*       __restrict__ s_in)   // shared [CT][4][WP] + scratch[16][512]
{
    constexpr int CT  = CIN + CH;
    constexpr int PH  = H / 2, PW = W / 2;
    constexpr int WP  = W + 4;                     // row stride: 16B multiple
    constexpr int NT  = (PW / 2) * CH;             // 512
    constexpr int TILE = CT * 4 * WP;

    float* scratch = s_in + TILE;                  // [16][NT], conflict-free

    const int ph = bid % PH;
    const int b  = bid / PH;
    const int r0 = 2 * ph;
    const int tid = threadIdx.x;

    // ---- stage input tile (x ‖ mem), 4 rows (halo), zero-padded cols -------
    for (int i = tid; i < TILE; i += NT) {
        int ch  = i / (4 * WP);
        int rem = i - ch * (4 * WP);
        int rr  = rem / WP;
        int cc  = rem - rr * WP;
        int r = r0 - 1 + rr;
        int c = cc - 1;
        float v = 0.f;
        if ((unsigned)r < (unsigned)H && (unsigned)c < (unsigned)W) {
            v = (ch < CIN) ? xin  [((b * CIN + ch)        * H + r) * W + c]
                           : memin[((b * CH  + (ch - CIN)) * H + r) * W + c];
        }
        s_in[i] = v;
    }
    __syncthreads();

    const int pwp = tid % (PW / 2);  // pooled-column pair index
    const int c   = tid / (PW / 2);  // hidden channel
    const int w0  = 4 * pwp;         // first raw column (16B-aligned smem idx)

    // ---- pass 1: gates f (1), o (3) -> park raw pre-activations in smem ----
    {
        float accF[8], accO[8];
        conv_gate_pair<CIN, CH, H, W>(s_in, wgt, bias, c, w0, 1, 3, accF, accO);
        #pragma unroll
        for (int p = 0; p < 8; p++) {
            scratch[p * NT + tid]       = accF[p];
            scratch[(8 + p) * NT + tid] = accO[p];
        }
    }

    // ---- pass 2: gates i (0), g (2) ------------------------------------------
    float accI[8], accG[8];
    conv_gate_pair<CIN, CH, H, W>(s_in, wgt, bias, c, w0, 0, 2, accI, accG);

    // ---- gate math + recurrence + maxpool + spike ----------------------------
    float mx0 = -1e30f, mx1 = -1e30f;
    #pragma unroll
    for (int pr = 0; pr < 2; pr++) {
        const int rowidx = ((b * CH + c) * H + (r0 + pr)) * W + w0;   // 16B-aligned
        float4 sv4 = *reinterpret_cast<const float4*>(syn + rowidx);
        float sv[4] = {sv4.x, sv4.y, sv4.z, sv4.w};
        float mv[4];
        #pragma unroll
        for (int j = 0; j < 4; j++) {
            const int p = pr * 4 + j;
            float gi = sigf(accI[p]);
            float gf = sigf(scratch[p * NT + tid]);
            float gg = tanh_acc(accG[p]);
            float go = sigf(scratch[(8 + p) * NT + tid]);
            float s = gf * sv[j] + gi * gg;
            sv[j] = s;
            float m = go * tanh_acc(s);
            mv[j] = m;
            if (j < 2) mx0 = fmaxf(mx0, m); else mx1 = fmaxf(mx1, m);
        }
        *reinterpret_cast<float4*>(syn    + rowidx) = make_float4(sv[0], sv[1], sv[2], sv[3]);
        *reinterpret_cast<float4*>(memout + rowidx) = make_float4(mv[0], mv[1], mv[2], mv[3]);
    }
    const int spkidx = ((b * CH + c) * PH + ph) * PW + 2 * pwp;
    spk[spkidx]     = (mx0 > THR) ? 1.f : 0.f;
    spk[spkidx + 1] = (mx1 > THR) ? 1.f : 0.f;
}

// ---------------- FC1 body: 64 tiles of 32m x 16n, 512 thr, 1 output each ---
__device__ __forceinline__ void fc1_layer(
    int bid,
    const float* __restrict__ spk3,  // (64, 2048)
    const float* __restrict__ w,     // (512, 2048)
    const float* __restrict__ bias,  // (512)
    float*       __restrict__ mem4,  // (64, 512) in-place
    float*       __restrict__ spk4,  // (64, 512)
    float*       __restrict__ smem)  // >= (32+16)*33 floats
{
    float* As = smem;            // [32][33]
    float* Bs = smem + 32 * 33;  // [16][33]
    const int tid   = threadIdx.x;
    const int mbase = (bid & 1) * 32;
    const int nbase = (bid >> 1) * 16;
    const int n = tid & 15;
    const int m = tid >> 4;      // 0..31
    float acc = 0.f;

    for (int kk = 0; kk < 2048; kk += 32) {
        for (int e = tid; e < 1024; e += 512) {
            int row = e >> 5, k = e & 31;
            As[row * 33 + k] = spk3[(mbase + row) * 2048 + kk + k];
        }
        {
            int row = tid >> 5, k = tid & 31;
            if (row < 16) Bs[row * 33 + k] = w[(size_t)(nbase + row) * 2048 + kk + k];
        }
        __syncthreads();
        #pragma unroll
        for (int k = 0; k < 32; k++)
            acc = fmaf(As[m * 33 + k], Bs[n * 33 + k], acc);
        __syncthreads();
    }

    const int ncol = nbase + n;
    float cur = acc + bias[ncol];
    int idx = (mbase + m) * 512 + ncol;
    float mo = mem4[idx];
    float reset = (mo > THR) ? THR : 0.f;           // reset from PREVIOUS mem
    float mn = BETA * mo + cur - reset;
    mem4[idx] = mn;
    spk4[idx] = ((mn - THR) > 0.f) ? 1.f : 0.f;
}

// ---------------- FC2 body ---------------------------------------------------
__device__ __forceinline__ void fc2_layer(
    const float* __restrict__ spk4,  // (64,512)
    const float* __restrict__ w,     // (2,512)
    const float* __restrict__ bias,  // (2)
    float*       __restrict__ mem5,  // (64,2)
    float*       __restrict__ out,   // [spk(25,64,2); mem(25,64,2)]
    int t)
{
    int tid = threadIdx.x;
    if (tid < 128) {
        int b = tid >> 1, o = tid & 1;
        const float* sr = spk4 + b * 512;
        const float* wr = w + o * 512;
        float s0 = 0.f, s1 = 0.f, s2 = 0.f, s3 = 0.f;
        #pragma unroll 4
        for (int k = 0; k < 512; k += 4) {
            s0 = fmaf(sr[k],     wr[k],     s0);
            s1 = fmaf(sr[k + 1], wr[k + 1], s1);
            s2 = fmaf(sr[k + 2], wr[k + 2], s2);
            s3 = fmaf(sr[k + 3], wr[k + 3], s3);
        }
        float acc = bias[o] + ((s0 + s1) + (s2 + s3));
        float mo = mem5[tid];
        float reset = (mo > THR) ? THR : 0.f;
        float mn = BETA * mo + acc - reset;
        mem5[tid] = mn;
        int oidx = (t * BATCH + b) * 2 + o;
        out[oidx] = ((mn - THR) > 0.f) ? 1.f : 0.f;    // spk_rec
        out[TSTEPS * BATCH * 2 + oidx] = mn;           // mem_rec
    }
}

// ---------------- persistent DAG kernel (timestep-contiguous slots) ----------
// Slot t (961 blocks): [0,512) L1(t) | [512,768) L2(t) | [768,896) L3(t) |
//                      [896,960) FC1(t) | [960] FC2(t)
// Every producer has strictly lower global bid; in-order dispatch + 2 CTA/SM
// keep spins harmless. Conv deps are per-batch (halos never cross batches).
__global__ void __launch_bounds__(512, 2)
dag_kernel(const float* __restrict__ x,
           const float* __restrict__ b1,
           const float* __restrict__ b2,
           const float* __restrict__ b3,
           const float* __restrict__ fc1w, const float* __restrict__ fc1b,
           const float* __restrict__ fc2w, const float* __restrict__ fc2b,
           float* __restrict__ out)
{
    extern __shared__ float smem[];
    const int t   = blockIdx.x / 961;
    const int bid = blockIdx.x % 961;
    const int p   = t & 1;

    if (bid < 512) {                               // ---- L1(t)
        int b = bid / 8;                           // PH = 8
        wait3(t >= 1 ? &g_cb[0][t - 1][b] : 0, 8,  // L1(t-1,b): own state
              t >= 2 ? &g_cb[1][t - 2][b] : 0, 4,  // L2(t-2,b): spk1 parity free
              0, 0);
        conv_layer<1, 16, 16, 128>(bid,
            x + (size_t)t * BATCH * 16 * 128,
            g_mem1[p], g_syn1, g_mem1[1 - p], g_spk1[p],
            g_wp_1, b1, smem);
        post_ptrs(&g_cb[0][t][b], 0);
    } else if (bid < 768) {                        // ---- L2(t)
        int b = (bid - 512) / 4;                   // PH = 4
        wait3(&g_cb[0][t][b], 8,                   // L1(t,b): input spikes
              t >= 1 ? &g_cb[1][t - 1][b] : 0, 4,  // L2(t-1,b): own state
              t >= 2 ? &g_cb[2][t - 2][b] : 0, 2); // L3(t-2,b): spk2 parity free
        conv_layer<16, 32, 8, 64>(bid - 512,
            g_spk1[p], g_mem2[p], g_syn2, g_mem2[1 - p], g_spk2[p],
            g_wp_2, b2, smem);
        post_ptrs(&g_cb[1][t][b], 0);
    } else if (bid < 896) {                        // ---- L3(t)
        int b = (bid - 768) / 2;                   // PH = 2
        wait3(&g_cb[1][t][b], 4,                   // L2(t,b): input spikes
              t >= 1 ? &g_cb[2][t - 1][b] : 0, 2,  // L3(t-1,b): own state
              t >= 2 ? &g_cnt[3][t - 2] : 0, 64);  // FC1(t-2): spk3 parity free
        conv_layer<32, 64, 4, 32>(bid - 768,
            g_spk2[p], g_mem3[p], g_syn3, g_mem3[1 - p], g_spk3[p],
            g_wp_3, b3, smem);
        post_ptrs(&g_cb[2][t][b], &g_l3h[t][b >> 5]);
    } else if (bid < 960) {                        // ---- FC1(t)
        int tile = bid - 896;
        int half = tile & 1;                       // mbase = half*32 -> batches
        wait3(&g_l3h[t][half], 64,                 // L3(t) blocks of this half
              t >= 1 ? &g_cnt[3][t - 1] : 0, 64,   // FC1(t-1): own state
              t >= 2 ? &g_cnt[4][t - 2] : 0, 1);   // FC2(t-2): spk4 parity free
        fc1_layer(tile, g_spk3[p], fc1w, fc1b, g_mem4, g_spk4[p], smem);
        post_ptrs(&g_cnt[3][t], 0);
    } else {                                       // ---- FC2(t)
        wait3(&g_cnt[3][t], 64,                    // FC1(t)
              t >= 1 ? &g_cnt[4][t - 1] : 0, 1,    // FC2(t-1): own state
              0, 0);
        fc2_layer(g_spk4[p], fc2w, fc2b, g_mem5, out, t);
        post_ptrs(&g_cnt[4][t], 0);
    }
}

// ---------------- host launcher ---------------------------------------------
extern "C" void kernel_launch(void* const* d_in, const int* in_sizes, int n_in,
                              void* d_out, int out_size) {
    const float* x    = (const float*)d_in[0];
    const float* w1   = (const float*)d_in[1];
    const float* b1   = (const float*)d_in[2];
    const float* w2   = (const float*)d_in[3];
    const float* b2   = (const float*)d_in[4];
    const float* w3   = (const float*)d_in[5];
    const float* b3   = (const float*)d_in[6];
    const float* fc1w = (const float*)d_in[7];
    const float* fc1b = (const float*)d_in[8];
    const float* fc2w = (const float*)d_in[9];
    const float* fc2b = (const float*)d_in[10];
    float* out = (float*)d_out;

    // smem: L3 tile 96*4*36*4 = 55,296 B + scratch 16*512*4 = 32,768 B
    // = 88,064 B per CTA; 2 CTA/SM -> 176,128 B (fits 228 KB carveout)
    constexpr int SMEM = 96 * 4 * 36 * 4 + 16 * 512 * 4;
    cudaFuncSetAttribute(dag_kernel,
                         cudaFuncAttributeMaxDynamicSharedMemorySize, SMEM);

    init_kernel<<<512, 256>>>(w1, w2, w3);
    dag_kernel<<<961 * TSTEPS, 512, SMEM>>>(x, b1, b2, b3,
                                            fc1w, fc1b, fc2w, fc2b, out);
}